// round 1
// baseline (speedup 1.0000x reference)
#include <cuda_runtime.h>
#include <cstdint>

#define N_NODES 50000
#define N_EDGES 800000
#define D 128

// Scratch for transformed = feat @ W  (static device global: allocation-free)
__device__ float g_tmp[(size_t)N_NODES * D];

// ---------------- f32x2 helpers (Blackwell packed fp32 FMA) ----------------

__device__ __forceinline__ unsigned long long pack_dup(float f) {
    unsigned long long r;
    asm("mov.b64 %0, {%1, %1};" : "=l"(r) : "f"(f));
    return r;
}

__device__ __forceinline__ void fma2(unsigned long long& acc,
                                     unsigned long long a,
                                     unsigned long long b) {
    asm("fma.rn.f32x2 %0, %1, %2, %3;" : "=l"(acc) : "l"(a), "l"(b), "l"(acc));
}

__device__ __forceinline__ float2 unpack2(unsigned long long v) {
    float2 r;
    asm("mov.b64 {%0, %1}, %2;" : "=f"(r.x), "=f"(r.y) : "l"(v));
    return r;
}

// ---------------- Kernel 1: fused dual GEMM --------------------------------
// out   = feat @ loop_W + bias
// g_tmp = feat @ W
// Block: 256 threads, 64 rows x 128 cols tile.
// Thread (tx=lane 0..31, ty=warp 0..7): rows ty*8..ty*8+7, cols 4*tx..4*tx+3.
// Both weight matrices live in SMEM (2 x 64KB); feat tile stored duplicated
// (each float as {f,f} in a 64-bit word, 64KB) so the f32x2 multiplier loads
// straight from SMEM as LDS.64 broadcast.

#define GEMM_SMEM_BYTES (2 * 128 * 128 * 4 + 64 * 128 * 8)  // 196608

__global__ __launch_bounds__(256) void fused_gemm(
    const float* __restrict__ feat, const float* __restrict__ W,
    const float* __restrict__ bias, const float* __restrict__ LW,
    float* __restrict__ out)
{
    extern __shared__ float smem[];
    float* ws  = smem;                 // 16384 floats: W [k][n]
    float* lws = smem + 16384;         // 16384 floats: loop_W [k][n]
    unsigned long long* fd =
        (unsigned long long*)(smem + 32768);  // 64*128 duplicated feat

    const int tid  = threadIdx.x;
    const int row0 = blockIdx.x * 64;

    // Load both weight matrices (float4, coalesced; L2-resident after wave 1)
    for (int i = tid * 4; i < 128 * 128; i += 256 * 4) {
        *(float4*)&ws[i]  = *(const float4*)&W[i];
        *(float4*)&lws[i] = *(const float4*)&LW[i];
    }
    // Load feat tile, duplicating each value into both f32x2 halves
    for (int i = tid; i < 64 * 128 / 4; i += 256) {
        int r = i >> 5;            // row within tile (32 float4 per row)
        int c = (i & 31) << 2;     // column
        int row = row0 + r;
        float4 v = make_float4(0.f, 0.f, 0.f, 0.f);
        if (row < N_NODES) v = *(const float4*)&feat[(size_t)row * D + c];
        unsigned long long* p = &fd[r * D + c];
        p[0] = pack_dup(v.x);
        p[1] = pack_dup(v.y);
        p[2] = pack_dup(v.z);
        p[3] = pack_dup(v.w);
    }
    __syncthreads();

    const int tx = tid & 31;
    const int ty = tid >> 5;
    const int rbase = ty * 8;

    unsigned long long aW[8][2], aL[8][2];
    #pragma unroll
    for (int r = 0; r < 8; r++) {
        aW[r][0] = 0ull; aW[r][1] = 0ull;
        aL[r][0] = 0ull; aL[r][1] = 0ull;
    }

    const float* wp = ws  + 4 * tx;
    const float* lp = lws + 4 * tx;
    const unsigned long long* fp = fd + rbase * D;

    #pragma unroll 2
    for (int k = 0; k < D; k++) {
        ulonglong2 wv = *(const ulonglong2*)(wp + k * D);  // cols 4tx..4tx+3 of W
        ulonglong2 lv = *(const ulonglong2*)(lp + k * D);  // of loop_W
        #pragma unroll
        for (int r = 0; r < 8; r++) {
            unsigned long long a = fp[r * D + k];          // {feat, feat}
            fma2(aW[r][0], a, wv.x);
            fma2(aW[r][1], a, wv.y);
            fma2(aL[r][0], a, lv.x);
            fma2(aL[r][1], a, lv.y);
        }
    }

    const float4 bv = *(const float4*)&bias[4 * tx];
    #pragma unroll
    for (int r = 0; r < 8; r++) {
        int row = row0 + rbase + r;
        if (row >= N_NODES) continue;
        float2 t0 = unpack2(aW[r][0]);
        float2 t1 = unpack2(aW[r][1]);
        *(float4*)&g_tmp[(size_t)row * D + 4 * tx] =
            make_float4(t0.x, t0.y, t1.x, t1.y);
        float2 o0 = unpack2(aL[r][0]);
        float2 o1 = unpack2(aL[r][1]);
        *(float4*)&out[(size_t)row * D + 4 * tx] =
            make_float4(o0.x + bv.x, o0.y + bv.y, o1.x + bv.z, o1.y + bv.w);
    }
}

// ---------------- Kernel 2: edge scatter -----------------------------------
// One warp per edge: 32 lanes x float4 = full 128-float row.
// Gather tmp[src] (coalesced 512B, L2-resident), atomic-add into out[dst].

__global__ __launch_bounds__(256) void scatter_edges(
    const int* __restrict__ src, const int* __restrict__ dst,
    float* __restrict__ out)
{
    long long gid = (long long)blockIdx.x * 256 + threadIdx.x;
    int edge = (int)(gid >> 5);
    if (edge >= N_EDGES) return;
    int lane = (int)(gid & 31);

    int s = src[edge];   // broadcast within warp
    int d = dst[edge];

    float4 v = *(const float4*)&g_tmp[(size_t)s * D + lane * 4];
    float* o = &out[(size_t)d * D + lane * 4];
    atomicAdd(o + 0, v.x);
    atomicAdd(o + 1, v.y);
    atomicAdd(o + 2, v.z);
    atomicAdd(o + 3, v.w);
}

// ---------------- Launch ----------------------------------------------------

extern "C" void kernel_launch(void* const* d_in, const int* in_sizes, int n_in,
                              void* d_out, int out_size)
{
    const float* feat = (const float*)d_in[0];
    const float* W    = (const float*)d_in[1];
    const float* bias = (const float*)d_in[2];
    const float* LW   = (const float*)d_in[3];
    const int*   src  = (const int*)d_in[4];
    const int*   dst  = (const int*)d_in[5];
    float* out = (float*)d_out;

    cudaFuncSetAttribute(fused_gemm,
                         cudaFuncAttributeMaxDynamicSharedMemorySize,
                         GEMM_SMEM_BYTES);

    fused_gemm<<<(N_NODES + 63) / 64, 256, GEMM_SMEM_BYTES>>>(feat, W, bias, LW, out);

    long long total_threads = (long long)N_EDGES * 32;
    int blocks = (int)((total_threads + 255) / 256);
    scatter_edges<<<blocks, 256>>>(src, dst, out);
}

// round 2
// speedup vs baseline: 1.6925x; 1.6925x over previous
#include <cuda_runtime.h>
#include <cstdint>

#define N_NODES 50000
#define N_EDGES 800000
#define D 128

// Scratch for transformed = feat @ W  (static device global: allocation-free)
__device__ float g_tmp[(size_t)N_NODES * D];

// ---------------- f32x2 helpers (Blackwell packed fp32 FMA) ----------------

__device__ __forceinline__ unsigned long long pack_dup(float f) {
    unsigned long long r;
    asm("mov.b64 %0, {%1, %1};" : "=l"(r) : "f"(f));
    return r;
}

__device__ __forceinline__ void fma2(unsigned long long& acc,
                                     unsigned long long a,
                                     unsigned long long b) {
    asm("fma.rn.f32x2 %0, %1, %2, %3;" : "=l"(acc) : "l"(a), "l"(b), "l"(acc));
}

__device__ __forceinline__ float2 unpack2(unsigned long long v) {
    float2 r;
    asm("mov.b64 {%0, %1}, %2;" : "=f"(r.x), "=f"(r.y) : "l"(v));
    return r;
}

// ---------------- Kernel 1: fused dual GEMM --------------------------------
// out   = feat @ loop_W + bias
// g_tmp = feat @ W
// Block: 256 threads, 64 rows x 128 cols tile.
// Both weight matrices live in SMEM (2 x 64KB); feat tile stored duplicated
// (each float as {f,f} in a 64-bit word, 64KB) so the f32x2 multiplier loads
// straight from SMEM as LDS.64 broadcast.

#define GEMM_SMEM_BYTES (2 * 128 * 128 * 4 + 64 * 128 * 8)  // 196608

__global__ __launch_bounds__(256) void fused_gemm(
    const float* __restrict__ feat, const float* __restrict__ W,
    const float* __restrict__ bias, const float* __restrict__ LW,
    float* __restrict__ out)
{
    extern __shared__ float smem[];
    float* ws  = smem;                 // 16384 floats: W [k][n]
    float* lws = smem + 16384;         // 16384 floats: loop_W [k][n]
    unsigned long long* fd =
        (unsigned long long*)(smem + 32768);  // 64*128 duplicated feat

    const int tid  = threadIdx.x;
    const int row0 = blockIdx.x * 64;

    // Load both weight matrices (float4, coalesced; L2-resident after wave 1)
    for (int i = tid * 4; i < 128 * 128; i += 256 * 4) {
        *(float4*)&ws[i]  = *(const float4*)&W[i];
        *(float4*)&lws[i] = *(const float4*)&LW[i];
    }
    // Load feat tile, duplicating each value into both f32x2 halves
    for (int i = tid; i < 64 * 128 / 4; i += 256) {
        int r = i >> 5;            // row within tile (32 float4 per row)
        int c = (i & 31) << 2;     // column
        int row = row0 + r;
        float4 v = make_float4(0.f, 0.f, 0.f, 0.f);
        if (row < N_NODES) v = *(const float4*)&feat[(size_t)row * D + c];
        unsigned long long* p = &fd[r * D + c];
        p[0] = pack_dup(v.x);
        p[1] = pack_dup(v.y);
        p[2] = pack_dup(v.z);
        p[3] = pack_dup(v.w);
    }
    __syncthreads();

    const int tx = tid & 31;
    const int ty = tid >> 5;
    const int rbase = ty * 8;

    unsigned long long aW[8][2], aL[8][2];
    #pragma unroll
    for (int r = 0; r < 8; r++) {
        aW[r][0] = 0ull; aW[r][1] = 0ull;
        aL[r][0] = 0ull; aL[r][1] = 0ull;
    }

    const float* wp = ws  + 4 * tx;
    const float* lp = lws + 4 * tx;
    const unsigned long long* fp = fd + rbase * D;

    #pragma unroll 2
    for (int k = 0; k < D; k++) {
        ulonglong2 wv = *(const ulonglong2*)(wp + k * D);  // cols 4tx..4tx+3 of W
        ulonglong2 lv = *(const ulonglong2*)(lp + k * D);  // of loop_W
        #pragma unroll
        for (int r = 0; r < 8; r++) {
            unsigned long long a = fp[r * D + k];          // {feat, feat}
            fma2(aW[r][0], a, wv.x);
            fma2(aW[r][1], a, wv.y);
            fma2(aL[r][0], a, lv.x);
            fma2(aL[r][1], a, lv.y);
        }
    }

    const float4 bv = *(const float4*)&bias[4 * tx];
    #pragma unroll
    for (int r = 0; r < 8; r++) {
        int row = row0 + rbase + r;
        if (row >= N_NODES) continue;
        float2 t0 = unpack2(aW[r][0]);
        float2 t1 = unpack2(aW[r][1]);
        *(float4*)&g_tmp[(size_t)row * D + 4 * tx] =
            make_float4(t0.x, t0.y, t1.x, t1.y);
        float2 o0 = unpack2(aL[r][0]);
        float2 o1 = unpack2(aL[r][1]);
        *(float4*)&out[(size_t)row * D + 4 * tx] =
            make_float4(o0.x + bv.x, o0.y + bv.y, o1.x + bv.z, o1.y + bv.w);
    }
}

// ---------------- Kernel 2: edge scatter -----------------------------------
// One warp per edge: 32 lanes x float4 = full 128-float row.
// Gather tmp[src] (coalesced 512B, L2-resident), then ONE red.global.add.v4
// per lane (RED.128) instead of 4 scalar atomics -> 4x fewer LSU ops.

__global__ __launch_bounds__(256) void scatter_edges(
    const int* __restrict__ src, const int* __restrict__ dst,
    float* __restrict__ out)
{
    long long gid = (long long)blockIdx.x * 256 + threadIdx.x;
    int edge = (int)(gid >> 5);
    if (edge >= N_EDGES) return;
    int lane = (int)(gid & 31);

    int s = src[edge];   // broadcast within warp
    int d = dst[edge];

    float4 v = *(const float4*)&g_tmp[(size_t)s * D + lane * 4];
    float* o = &out[(size_t)d * D + lane * 4];
    asm volatile("red.global.add.v4.f32 [%0], {%1, %2, %3, %4};"
                 :: "l"(o), "f"(v.x), "f"(v.y), "f"(v.z), "f"(v.w)
                 : "memory");
}

// ---------------- Launch ----------------------------------------------------

extern "C" void kernel_launch(void* const* d_in, const int* in_sizes, int n_in,
                              void* d_out, int out_size)
{
    const float* feat = (const float*)d_in[0];
    const float* W    = (const float*)d_in[1];
    const float* bias = (const float*)d_in[2];
    const float* LW   = (const float*)d_in[3];
    const int*   src  = (const int*)d_in[4];
    const int*   dst  = (const int*)d_in[5];
    float* out = (float*)d_out;

    cudaFuncSetAttribute(fused_gemm,
                         cudaFuncAttributeMaxDynamicSharedMemorySize,
                         GEMM_SMEM_BYTES);

    fused_gemm<<<(N_NODES + 63) / 64, 256, GEMM_SMEM_BYTES>>>(feat, W, bias, LW, out);

    long long total_threads = (long long)N_EDGES * 32;
    int blocks = (int)((total_threads + 255) / 256);
    scatter_edges<<<blocks, 256>>>(src, dst, out);
}

// round 6
// speedup vs baseline: 1.8930x; 1.1185x over previous
#include <cuda_runtime.h>
#include <cstdint>

#define N_NODES 50000
#define N_EDGES 800000
#define D 128

// ---------------- static device scratch (allocation-free) -------------------
__device__ float g_tmp[(size_t)N_NODES * D];   // feat @ W
__device__ int   g_count[N_NODES];
__device__ int   g_offsets[N_NODES];           // exclusive prefix of count
__device__ int   g_cursor[N_NODES];
__device__ int   g_blocksums[256];
__device__ int   g_csr_src[N_EDGES];

// ---------------- f32x2 helpers (Blackwell packed fp32 FMA) ----------------

__device__ __forceinline__ unsigned long long pack_dup(float f) {
    unsigned long long r;
    asm("mov.b64 %0, {%1, %1};" : "=l"(r) : "f"(f));
    return r;
}

__device__ __forceinline__ void fma2(unsigned long long& acc,
                                     unsigned long long a,
                                     unsigned long long b) {
    asm("fma.rn.f32x2 %0, %1, %2, %3;" : "=l"(acc) : "l"(a), "l"(b), "l"(acc));
}

__device__ __forceinline__ float2 unpack2(unsigned long long v) {
    float2 r;
    asm("mov.b64 {%0, %1}, %2;" : "=f"(r.x), "=f"(r.y) : "l"(v));
    return r;
}

// ---------------- Kernel 1: fused dual GEMM --------------------------------
// out   = feat @ loop_W + bias ; g_tmp = feat @ W
// R6 change: k-unrolled by 2; 'a' operand loaded as LDS.128 (2 k-steps per
// load, warp-uniform broadcast) -> ~15% fewer issue slots in the hot loop.

#define GEMM_SMEM_BYTES (2 * 128 * 128 * 4 + 64 * 128 * 8)  // 196608

__global__ __launch_bounds__(256) void fused_gemm(
    const float* __restrict__ feat, const float* __restrict__ W,
    const float* __restrict__ bias, const float* __restrict__ LW,
    float* __restrict__ out)
{
    extern __shared__ float smem[];
    float* ws  = smem;
    float* lws = smem + 16384;
    unsigned long long* fd = (unsigned long long*)(smem + 32768);

    const int tid  = threadIdx.x;
    const int row0 = blockIdx.x * 64;

    for (int i = tid * 4; i < 128 * 128; i += 256 * 4) {
        *(float4*)&ws[i]  = *(const float4*)&W[i];
        *(float4*)&lws[i] = *(const float4*)&LW[i];
    }
    for (int i = tid; i < 64 * 128 / 4; i += 256) {
        int r = i >> 5;
        int c = (i & 31) << 2;
        int row = row0 + r;
        float4 v = make_float4(0.f, 0.f, 0.f, 0.f);
        if (row < N_NODES) v = *(const float4*)&feat[(size_t)row * D + c];
        unsigned long long* p = &fd[r * D + c];
        p[0] = pack_dup(v.x);
        p[1] = pack_dup(v.y);
        p[2] = pack_dup(v.z);
        p[3] = pack_dup(v.w);
    }
    __syncthreads();

    const int tx = tid & 31;
    const int ty = tid >> 5;
    const int rbase = ty * 8;

    unsigned long long aW[8][2], aL[8][2];
    #pragma unroll
    for (int r = 0; r < 8; r++) {
        aW[r][0] = 0ull; aW[r][1] = 0ull;
        aL[r][0] = 0ull; aL[r][1] = 0ull;
    }

    const float* wp = ws  + 4 * tx;
    const float* lp = lws + 4 * tx;
    const unsigned long long* fp = fd + rbase * D;

    #pragma unroll 2
    for (int k = 0; k < D; k += 2) {
        ulonglong2 wv0 = *(const ulonglong2*)(wp + k * D);
        ulonglong2 lv0 = *(const ulonglong2*)(lp + k * D);
        ulonglong2 wv1 = *(const ulonglong2*)(wp + (k + 1) * D);
        ulonglong2 lv1 = *(const ulonglong2*)(lp + (k + 1) * D);
        #pragma unroll
        for (int r = 0; r < 8; r++) {
            // {a_k, a_k} and {a_{k+1}, a_{k+1}} in one 128-bit broadcast load
            ulonglong2 a2 = *(const ulonglong2*)&fp[r * D + k];
            fma2(aW[r][0], a2.x, wv0.x);
            fma2(aW[r][1], a2.x, wv0.y);
            fma2(aL[r][0], a2.x, lv0.x);
            fma2(aL[r][1], a2.x, lv0.y);
            fma2(aW[r][0], a2.y, wv1.x);
            fma2(aW[r][1], a2.y, wv1.y);
            fma2(aL[r][0], a2.y, lv1.x);
            fma2(aL[r][1], a2.y, lv1.y);
        }
    }

    const float4 bv = *(const float4*)&bias[4 * tx];
    #pragma unroll
    for (int r = 0; r < 8; r++) {
        int row = row0 + rbase + r;
        if (row >= N_NODES) continue;
        float2 t0 = unpack2(aW[r][0]);
        float2 t1 = unpack2(aW[r][1]);
        *(float4*)&g_tmp[(size_t)row * D + 4 * tx] =
            make_float4(t0.x, t0.y, t1.x, t1.y);
        float2 o0 = unpack2(aL[r][0]);
        float2 o1 = unpack2(aL[r][1]);
        *(float4*)&out[(size_t)row * D + 4 * tx] =
            make_float4(o0.x + bv.x, o0.y + bv.y, o1.x + bv.z, o1.y + bv.w);
    }
}

// ---------------- CSR construction ------------------------------------------

__global__ void zero_counts() {
    int i = blockIdx.x * blockDim.x + threadIdx.x;
    if (i < N_NODES) g_count[i] = 0;
}

__global__ void hist_dst(const int* __restrict__ dst) {
    int e = blockIdx.x * blockDim.x + threadIdx.x;
    if (e < N_EDGES) atomicAdd(&g_count[dst[e]], 1);
}

__device__ __forceinline__ int warp_incl_scan(int x, int lane) {
    #pragma unroll
    for (int d = 1; d < 32; d <<= 1) {
        int y = __shfl_up_sync(0xffffffffu, x, d);
        if (lane >= d) x += y;
    }
    return x;
}

// Per-block exclusive scan of g_count -> g_offsets (local), block total -> g_blocksums
__global__ __launch_bounds__(256) void scan_local() {
    __shared__ int wsum[8];
    int i = blockIdx.x * 256 + threadIdx.x;
    int lane = threadIdx.x & 31;
    int wid  = threadIdx.x >> 5;
    int v = (i < N_NODES) ? g_count[i] : 0;
    int inc = warp_incl_scan(v, lane);
    if (lane == 31) wsum[wid] = inc;
    __syncthreads();
    if (wid == 0) {
        int s = (lane < 8) ? wsum[lane] : 0;
        int si = warp_incl_scan(s, lane);
        if (lane < 8) wsum[lane] = si - s;   // exclusive warp prefix
    }
    __syncthreads();
    int excl = inc - v + wsum[wid];
    if (i < N_NODES) g_offsets[i] = excl;
    if (threadIdx.x == 255) g_blocksums[blockIdx.x] = excl + v;
}

// Single block: exclusive scan of block sums (nblocks <= 256)
__global__ __launch_bounds__(256) void scan_sums(int nblocks) {
    __shared__ int wsum[8];
    int t = threadIdx.x;
    int lane = t & 31;
    int wid  = t >> 5;
    int v = (t < nblocks) ? g_blocksums[t] : 0;
    int inc = warp_incl_scan(v, lane);
    if (lane == 31) wsum[wid] = inc;
    __syncthreads();
    if (wid == 0) {
        int s = (lane < 8) ? wsum[lane] : 0;
        int si = warp_incl_scan(s, lane);
        if (lane < 8) wsum[lane] = si - s;
    }
    __syncthreads();
    if (t < nblocks) g_blocksums[t] = inc - v + wsum[wid];
}

__global__ __launch_bounds__(256) void scan_finalize() {
    int i = blockIdx.x * 256 + threadIdx.x;
    if (i < N_NODES) {
        int o = g_offsets[i] + g_blocksums[blockIdx.x];
        g_offsets[i] = o;
        g_cursor[i]  = o;
    }
}

__global__ void reorder_edges(const int* __restrict__ src,
                              const int* __restrict__ dst) {
    int e = blockIdx.x * blockDim.x + threadIdx.x;
    if (e < N_EDGES) {
        int pos = atomicAdd(&g_cursor[dst[e]], 1);
        g_csr_src[pos] = src[e];
    }
}

// ---------------- Kernel 3: warp-per-node gather aggregate ------------------
// out[n] += sum over incoming edges of g_tmp[src]. No atomics.

__global__ __launch_bounds__(256) void aggregate_nodes(float* __restrict__ out)
{
    int warp = (blockIdx.x * 256 + threadIdx.x) >> 5;
    if (warp >= N_NODES) return;
    int lane = threadIdx.x & 31;

    int off = g_offsets[warp];
    int cnt = g_count[warp];
    if (cnt == 0) return;

    float4 acc0 = make_float4(0.f, 0.f, 0.f, 0.f);
    float4 acc1 = make_float4(0.f, 0.f, 0.f, 0.f);

    for (int base = 0; base < cnt; base += 32) {
        int m = cnt - base; if (m > 32) m = 32;
        int myidx = (lane < m) ? g_csr_src[off + base + lane] : 0;
        int j = 0;
        for (; j + 1 < m; j += 2) {
            int s0 = __shfl_sync(0xffffffffu, myidx, j);
            int s1 = __shfl_sync(0xffffffffu, myidx, j + 1);
            float4 v0 = *(const float4*)&g_tmp[(size_t)s0 * D + lane * 4];
            float4 v1 = *(const float4*)&g_tmp[(size_t)s1 * D + lane * 4];
            acc0.x += v0.x; acc0.y += v0.y; acc0.z += v0.z; acc0.w += v0.w;
            acc1.x += v1.x; acc1.y += v1.y; acc1.z += v1.z; acc1.w += v1.w;
        }
        if (j < m) {
            int s0 = __shfl_sync(0xffffffffu, myidx, j);
            float4 v0 = *(const float4*)&g_tmp[(size_t)s0 * D + lane * 4];
            acc0.x += v0.x; acc0.y += v0.y; acc0.z += v0.z; acc0.w += v0.w;
        }
    }

    float4* op = (float4*)&out[(size_t)warp * D + lane * 4];
    float4 o = *op;
    o.x += acc0.x + acc1.x;
    o.y += acc0.y + acc1.y;
    o.z += acc0.z + acc1.z;
    o.w += acc0.w + acc1.w;
    *op = o;
}

// ---------------- Launch ----------------------------------------------------

extern "C" void kernel_launch(void* const* d_in, const int* in_sizes, int n_in,
                              void* d_out, int out_size)
{
    const float* feat = (const float*)d_in[0];
    const float* W    = (const float*)d_in[1];
    const float* bias = (const float*)d_in[2];
    const float* LW   = (const float*)d_in[3];
    const int*   src  = (const int*)d_in[4];
    const int*   dst  = (const int*)d_in[5];
    float* out = (float*)d_out;

    const int scanBlocks = (N_NODES + 255) / 256;   // 196

    // CSR build (depends only on src/dst)
    zero_counts<<<scanBlocks, 256>>>();
    hist_dst<<<(N_EDGES + 255) / 256, 256>>>(dst);
    scan_local<<<scanBlocks, 256>>>();
    scan_sums<<<1, 256>>>(scanBlocks);
    scan_finalize<<<scanBlocks, 256>>>();
    reorder_edges<<<(N_EDGES + 255) / 256, 256>>>(src, dst);

    // GEMM
    cudaFuncSetAttribute(fused_gemm,
                         cudaFuncAttributeMaxDynamicSharedMemorySize,
                         GEMM_SMEM_BYTES);
    fused_gemm<<<(N_NODES + 63) / 64, 256, GEMM_SMEM_BYTES>>>(feat, W, bias, LW, out);

    // Aggregate (reads g_tmp + CSR, plain stores)
    aggregate_nodes<<<(N_NODES * 32 + 255) / 256, 256>>>(out);
}

// round 15
// speedup vs baseline: 2.6866x; 1.4192x over previous
#include <cuda_runtime.h>
#include <cuda_bf16.h>
#include <cstdint>

#define N_NODES 50000
#define N_EDGES 800000
#define D 128

// ---------------- static device scratch (allocation-free) -------------------
__device__ float g_tmp[(size_t)N_NODES * D];   // feat @ W
__device__ int   g_count[N_NODES];
__device__ int   g_offsets[N_NODES];
__device__ int   g_cursor[N_NODES];
__device__ int   g_blocksums[256];
__device__ int   g_csr_src[N_EDGES];

// Packed bf16 weight fragments in mma.sync B-register order.
// Images: 0 = W_hi, 1 = W_lo, 2 = LW_hi, 3 = LW_lo. Each 8192 uint32 (32 KB).
__device__ __align__(16) uint32_t g_pk[4 * 8192];

// ---------------- helpers ---------------------------------------------------

__device__ __forceinline__ uint32_t smem_u32(const void* p) {
    uint32_t a;
    asm("{ .reg .u64 t; cvta.to.shared.u64 t, %1; cvt.u32.u64 %0, t; }"
        : "=r"(a) : "l"(p));
    return a;
}

// ldmatrix x4: loads the 4 8x8 bf16 matrices of a 16x16 A tile
#define LDSM_X4(r, a)                                                        \
    asm volatile("ldmatrix.sync.aligned.m8n8.x4.shared.b16 "                 \
                 "{%0, %1, %2, %3}, [%4];"                                   \
                 : "=r"((r)[0]), "=r"((r)[1]), "=r"((r)[2]), "=r"((r)[3])    \
                 : "r"(a))

__device__ __forceinline__ void mma_bf16(float* c, const uint32_t* a,
                                         uint32_t b0, uint32_t b1) {
    asm volatile(
        "mma.sync.aligned.m16n8k16.row.col.f32.bf16.bf16.f32 "
        "{%0, %1, %2, %3}, {%4, %5, %6, %7}, {%8, %9}, {%0, %1, %2, %3};"
        : "+f"(c[0]), "+f"(c[1]), "+f"(c[2]), "+f"(c[3])
        : "r"(a[0]), "r"(a[1]), "r"(a[2]), "r"(a[3]), "r"(b0), "r"(b1));
}

__device__ __forceinline__ uint32_t pack_bf16x2(__nv_bfloat16 lo, __nv_bfloat16 hi) {
    __nv_bfloat162 p = __halves2bfloat162(lo, hi);
    return *(uint32_t*)&p;
}

// ---------------- Kernel 0: weight prep -------------------------------------
// Emits W/LW hi/lo bf16 in exact per-thread mma B-fragment order:
// uint32 index = img*8192 + frag*64 + lane*2 + reg, frag = ktile*16 + ntile.
// Thread's b-reg pair = {B[k][n], B[k+1][n]}, k = ktile*16 + (lane%4)*2 + reg*8,
// n = ntile*8 + lane/4.

__global__ __launch_bounds__(256) void weight_prep(
    const float* __restrict__ W, const float* __restrict__ LW)
{
    int idx = blockIdx.x * 256 + threadIdx.x;
    if (idx >= 32768) return;
    int img  = idx >> 13;
    int rem  = idx & 8191;
    int frag = rem >> 6;
    int lane = (rem >> 1) & 31;
    int reg  = rem & 1;

    int k = (frag >> 4) * 16 + (lane & 3) * 2 + reg * 8;
    int n = (frag & 15) * 8 + (lane >> 2);

    const float* src = (img >= 2) ? LW : W;
    float f0 = src[k * 128 + n];
    float f1 = src[(k + 1) * 128 + n];

    __nv_bfloat16 h0 = __float2bfloat16_rn(f0);
    __nv_bfloat16 h1 = __float2bfloat16_rn(f1);
    uint32_t val;
    if (img & 1) {  // lo image
        __nv_bfloat16 l0 = __float2bfloat16_rn(f0 - __bfloat162float(h0));
        __nv_bfloat16 l1 = __float2bfloat16_rn(f1 - __bfloat162float(h1));
        val = pack_bf16x2(l0, l1);
    } else {        // hi image
        val = pack_bf16x2(h0, h1);
    }
    g_pk[idx] = val;
}

// ---------------- Kernel 1: HMMA dual GEMM ----------------------------------
// g_tmp = feat @ W ; out = feat @ LW + bias.  Split-bf16, 3 passes.
// 1 CTA per 128 rows, 256 threads, warp w handles rows w*16..w*16+15.

#define ASTRIDE 272                          // 136 bf16 per row (pad kills conflicts)
#define SM_AHI  0
#define SM_ALO  34816                        // 128*272
#define SM_PK   69632
#define HM_SMEM_TOTAL (69632 + 4 * 32768)    // 200704

__global__ __launch_bounds__(256, 1) void gemm_tc(
    const float* __restrict__ feat, const float* __restrict__ bias,
    float* __restrict__ outp)
{
    extern __shared__ char smem[];
    const uint32_t sb = smem_u32(smem);
    const int tid  = threadIdx.x;
    const int wid  = tid >> 5;
    const int lane = tid & 31;
    const int row0 = blockIdx.x * 128;

    // Copy packed weight fragments (131072 B, linear)
    {
        const uint4* s = (const uint4*)g_pk;
        uint4* d = (uint4*)(smem + SM_PK);
        #pragma unroll
        for (int i = tid; i < 8192; i += 256) d[i] = s[i];
    }

    // Load + split-convert feat tile into A_hi / A_lo (row-major, padded)
    for (int i = tid; i < 4096; i += 256) {      // 128 rows x 32 float4
        int r  = i >> 5;
        int c  = (i & 31) * 4;                   // element column
        int row = row0 + r;
        float4 v = make_float4(0.f, 0.f, 0.f, 0.f);
        if (row < N_NODES) v = *(const float4*)&feat[(size_t)row * D + c];
        __nv_bfloat16 h0 = __float2bfloat16_rn(v.x);
        __nv_bfloat16 h1 = __float2bfloat16_rn(v.y);
        __nv_bfloat16 h2 = __float2bfloat16_rn(v.z);
        __nv_bfloat16 h3 = __float2bfloat16_rn(v.w);
        __nv_bfloat16 l0 = __float2bfloat16_rn(v.x - __bfloat162float(h0));
        __nv_bfloat16 l1 = __float2bfloat16_rn(v.y - __bfloat162float(h1));
        __nv_bfloat16 l2 = __float2bfloat16_rn(v.z - __bfloat162float(h2));
        __nv_bfloat16 l3 = __float2bfloat16_rn(v.w - __bfloat162float(h3));
        char* ph = smem + SM_AHI + r * ASTRIDE + c * 2;
        char* pl = smem + SM_ALO + r * ASTRIDE + c * 2;
        *(uint32_t*)(ph)     = pack_bf16x2(h0, h1);
        *(uint32_t*)(ph + 4) = pack_bf16x2(h2, h3);
        *(uint32_t*)(pl)     = pack_bf16x2(l0, l1);
        *(uint32_t*)(pl + 4) = pack_bf16x2(l2, l3);
    }
    __syncthreads();

    // Accumulators: 2 outputs x 16 n-tiles x 4 f32
    float acc[2][16][4];
    #pragma unroll
    for (int o = 0; o < 2; o++)
        #pragma unroll
        for (int nt = 0; nt < 16; nt++)
            #pragma unroll
            for (int q = 0; q < 4; q++) acc[o][nt][q] = 0.f;

    // ldmatrix address for this lane: matrix m = lane/8, row-in-matrix = lane%8
    const int m  = lane >> 3;
    const int rr = lane & 7;
    const int a_row = wid * 16 + (m & 1) * 8 + rr;
    const uint32_t a_coloff = (uint32_t)((m >> 1) * 16);   // +8 halves = 16B
    const uint32_t addr_hi0 = sb + SM_AHI + a_row * ASTRIDE + a_coloff;
    const uint32_t addr_lo0 = sb + SM_ALO + a_row * ASTRIDE + a_coloff;

    #pragma unroll
    for (int kt = 0; kt < 8; kt++) {
        uint32_t ah[4], al[4];
        LDSM_X4(ah, addr_hi0 + kt * 32);
        LDSM_X4(al, addr_lo0 + kt * 32);
        #pragma unroll
        for (int o = 0; o < 2; o++) {
            const char* hi_base = smem + SM_PK + (o * 2)     * 32768;
            const char* lo_base = smem + SM_PK + (o * 2 + 1) * 32768;
            #pragma unroll
            for (int nt = 0; nt < 16; nt++) {
                uint32_t off = (uint32_t)(((kt * 16 + nt) * 64 + lane * 2) * 4);
                uint2 bh = *(const uint2*)(hi_base + off);
                uint2 bl = *(const uint2*)(lo_base + off);
                mma_bf16(acc[o][nt], ah, bh.x, bh.y);
                mma_bf16(acc[o][nt], ah, bl.x, bl.y);
                mma_bf16(acc[o][nt], al, bh.x, bh.y);
            }
        }
    }

    // Epilogue: thread holds C[r][c],C[r][c+1],C[r+8][c],C[r+8][c+1]
    const int row_lo = row0 + wid * 16 + (lane >> 2);
    const int row_hi = row_lo + 8;
    const int cbase  = (lane & 3) * 2;
    #pragma unroll
    for (int nt = 0; nt < 16; nt++) {
        int c = nt * 8 + cbase;
        float2 bv = *(const float2*)&bias[c];
        if (row_lo < N_NODES) {
            *(float2*)&g_tmp[(size_t)row_lo * D + c] =
                make_float2(acc[0][nt][0], acc[0][nt][1]);
            *(float2*)&outp[(size_t)row_lo * D + c] =
                make_float2(acc[1][nt][0] + bv.x, acc[1][nt][1] + bv.y);
        }
        if (row_hi < N_NODES) {
            *(float2*)&g_tmp[(size_t)row_hi * D + c] =
                make_float2(acc[0][nt][2], acc[0][nt][3]);
            *(float2*)&outp[(size_t)row_hi * D + c] =
                make_float2(acc[1][nt][2] + bv.x, acc[1][nt][3] + bv.y);
        }
    }
}

// ---------------- CSR construction (unchanged) ------------------------------

__global__ void zero_counts() {
    int i = blockIdx.x * blockDim.x + threadIdx.x;
    if (i < N_NODES) g_count[i] = 0;
}

__global__ void hist_dst(const int* __restrict__ dst) {
    int e = blockIdx.x * blockDim.x + threadIdx.x;
    if (e < N_EDGES) atomicAdd(&g_count[dst[e]], 1);
}

__device__ __forceinline__ int warp_incl_scan(int x, int lane) {
    #pragma unroll
    for (int d = 1; d < 32; d <<= 1) {
        int y = __shfl_up_sync(0xffffffffu, x, d);
        if (lane >= d) x += y;
    }
    return x;
}

__global__ __launch_bounds__(256) void scan_local() {
    __shared__ int wsum[8];
    int i = blockIdx.x * 256 + threadIdx.x;
    int lane = threadIdx.x & 31;
    int wid  = threadIdx.x >> 5;
    int v = (i < N_NODES) ? g_count[i] : 0;
    int inc = warp_incl_scan(v, lane);
    if (lane == 31) wsum[wid] = inc;
    __syncthreads();
    if (wid == 0) {
        int s = (lane < 8) ? wsum[lane] : 0;
        int si = warp_incl_scan(s, lane);
        if (lane < 8) wsum[lane] = si - s;
    }
    __syncthreads();
    int excl = inc - v + wsum[wid];
    if (i < N_NODES) g_offsets[i] = excl;
    if (threadIdx.x == 255) g_blocksums[blockIdx.x] = excl + v;
}

__global__ __launch_bounds__(256) void scan_sums(int nblocks) {
    __shared__ int wsum[8];
    int t = threadIdx.x;
    int lane = t & 31;
    int wid  = t >> 5;
    int v = (t < nblocks) ? g_blocksums[t] : 0;
    int inc = warp_incl_scan(v, lane);
    if (lane == 31) wsum[wid] = inc;
    __syncthreads();
    if (wid == 0) {
        int s = (lane < 8) ? wsum[lane] : 0;
        int si = warp_incl_scan(s, lane);
        if (lane < 8) wsum[lane] = si - s;
    }
    __syncthreads();
    if (t < nblocks) g_blocksums[t] = inc - v + wsum[wid];
}

__global__ __launch_bounds__(256) void scan_finalize() {
    int i = blockIdx.x * 256 + threadIdx.x;
    if (i < N_NODES) {
        int o = g_offsets[i] + g_blocksums[blockIdx.x];
        g_offsets[i] = o;
        g_cursor[i]  = o;
    }
}

__global__ void reorder_edges(const int* __restrict__ src,
                              const int* __restrict__ dst) {
    int e = blockIdx.x * blockDim.x + threadIdx.x;
    if (e < N_EDGES) {
        int pos = atomicAdd(&g_cursor[dst[e]], 1);
        g_csr_src[pos] = src[e];
    }
}

// ---------------- Kernel 3: warp-per-node gather aggregate ------------------

__global__ __launch_bounds__(256) void aggregate_nodes(float* __restrict__ out)
{
    int warp = (blockIdx.x * 256 + threadIdx.x) >> 5;
    if (warp >= N_NODES) return;
    int lane = threadIdx.x & 31;

    int off = g_offsets[warp];
    int cnt = g_count[warp];
    if (cnt == 0) return;

    float4 acc0 = make_float4(0.f, 0.f, 0.f, 0.f);
    float4 acc1 = make_float4(0.f, 0.f, 0.f, 0.f);

    for (int base = 0; base < cnt; base += 32) {
        int m = cnt - base; if (m > 32) m = 32;
        int myidx = (lane < m) ? g_csr_src[off + base + lane] : 0;
        int j = 0;
        for (; j + 1 < m; j += 2) {
            int s0 = __shfl_sync(0xffffffffu, myidx, j);
            int s1 = __shfl_sync(0xffffffffu, myidx, j + 1);
            float4 v0 = *(const float4*)&g_tmp[(size_t)s0 * D + lane * 4];
            float4 v1 = *(const float4*)&g_tmp[(size_t)s1 * D + lane * 4];
            acc0.x += v0.x; acc0.y += v0.y; acc0.z += v0.z; acc0.w += v0.w;
            acc1.x += v1.x; acc1.y += v1.y; acc1.z += v1.z; acc1.w += v1.w;
        }
        if (j < m) {
            int s0 = __shfl_sync(0xffffffffu, myidx, j);
            float4 v0 = *(const float4*)&g_tmp[(size_t)s0 * D + lane * 4];
            acc0.x += v0.x; acc0.y += v0.y; acc0.z += v0.z; acc0.w += v0.w;
        }
    }

    float4* op = (float4*)&out[(size_t)warp * D + lane * 4];
    float4 o = *op;
    o.x += acc0.x + acc1.x;
    o.y += acc0.y + acc1.y;
    o.z += acc0.z + acc1.z;
    o.w += acc0.w + acc1.w;
    *op = o;
}

// ---------------- Launch ----------------------------------------------------

extern "C" void kernel_launch(void* const* d_in, const int* in_sizes, int n_in,
                              void* d_out, int out_size)
{
    const float* feat = (const float*)d_in[0];
    const float* W    = (const float*)d_in[1];
    const float* bias = (const float*)d_in[2];
    const float* LW   = (const float*)d_in[3];
    const int*   src  = (const int*)d_in[4];
    const int*   dst  = (const int*)d_in[5];
    float* out = (float*)d_out;

    const int scanBlocks = (N_NODES + 255) / 256;   // 196

    // Weight conversion into fragment order
    weight_prep<<<128, 256>>>(W, LW);

    // CSR build (depends only on src/dst)
    zero_counts<<<scanBlocks, 256>>>();
    hist_dst<<<(N_EDGES + 255) / 256, 256>>>(dst);
    scan_local<<<scanBlocks, 256>>>();
    scan_sums<<<1, 256>>>(scanBlocks);
    scan_finalize<<<scanBlocks, 256>>>();
    reorder_edges<<<(N_EDGES + 255) / 256, 256>>>(src, dst);

    // HMMA dual GEMM
    cudaFuncSetAttribute(gemm_tc,
                         cudaFuncAttributeMaxDynamicSharedMemorySize,
                         HM_SMEM_TOTAL);
    gemm_tc<<<(N_NODES + 127) / 128, 256, HM_SMEM_TOTAL>>>(feat, bias, out);

    // Aggregate (reads g_tmp + CSR, plain stores)
    aggregate_nodes<<<(N_NODES * 32 + 255) / 256, 256>>>(out);
}